// round 7
// baseline (speedup 1.0000x reference)
#include <cuda_runtime.h>

#define HH    512
#define WW    512
#define HW    (HH * WW)
#define PAD   8
#define NKH   32
#define NKW   32
#define NK    1024
#define NC    33            // stride cells per dim (528/16)
#define BATCH 64
#define RPAD  36            // padded smem row (words): conflict-free LDS.128

// Init: out[b,n] = bias[n]. Full overwrite -> graph-replay idempotent.
__global__ __launch_bounds__(256) void bslc_init(
    const float* __restrict__ bias, float* __restrict__ out)
{
    const int idx = blockIdx.x * 256 + threadIdx.x;   // b*NK + n
    out[idx] = bias[idx & (NK - 1)];
}

// One block per HALF of a 16x16 stride cell (16 wide x 8 rows).
// Cell (Ri,Ci) covers padded pixels [16Ri,16Ri+16) x [16Ci,16Ci+16); these
// feed windows (Ri-i, Ci-j), i,j in {0,1}, at kernel offsets (dy+16i,
// dx+16j) -> quadrants q = i*2+j.
//
// Warp w owns batches 8w..8w+7. Lane l owns ONE pixel-quad of the half:
// dy = half*8 + (l>>2), dx4 = (l&3)*4. Per batch: 1 coalesced LDG.128
// (x read exactly once), 16 FMAs against 4 register-held quadrant weights,
// 4 conflict-free STS. Phase 2: thread (b,q) sums its 32-lane row via 8
// conflict-free LDS.128 and atomicAdds into bias-initialized out.
__global__ __launch_bounds__(256, 5) void bslc_main(
    const float* __restrict__ x,       // (64,1,512,512)
    const float* __restrict__ weight,  // (NK,1024)
    float* __restrict__ out)           // (64,NK) = bias-initialized
{
    // [warp][batch-in-warp][quadrant][lane + pad]
    __shared__ __align__(16) float sred[8][8][4][RPAD];

    const int cell = blockIdx.x;
    const int half = blockIdx.y;
    const int Ri = cell / NC, Ci = cell % NC;
    const int tid  = threadIdx.x;
    const int lane = tid & 31;
    const int warp = tid >> 5;

    // Quadrant windows + validity (uniform across block, full 4-sided check)
    int nq[4]; bool vq[4];
#pragma unroll
    for (int q = 0; q < 4; q++) {
        const int r = Ri - (q >> 1), c = Ci - (q & 1);
        vq[q] = (r >= 0) && (r < NKH) && (c >= 0) && (c < NKW);
        nq[q] = vq[q] ? (r * NKW + c) : 0;
    }

    // Lane's pixel-quad within this half-cell
    const int dy  = half * 8 + (lane >> 2);
    const int dx4 = (lane & 3) << 2;

    float4 wq[4];
#pragma unroll
    for (int q = 0; q < 4; q++) {
        float4 w = make_float4(0.f, 0.f, 0.f, 0.f);
        if (vq[q])
            w = *reinterpret_cast<const float4*>(
                    weight + nq[q] * 1024
                           + (dy  + 16 * (q >> 1)) * 32
                           + (dx4 + 16 * (q & 1)));
        wq[q] = w;
    }

    const int  uy = Ri * 16 + dy  - PAD;
    const int  ux = Ci * 16 + dx4 - PAD;
    const bool ok = ((unsigned)uy < (unsigned)HH) &&
                    ((unsigned)ux <= (unsigned)(WW - 4));
    const int  off = uy * WW + ux;

    const int b0 = warp * 8;
    const float* __restrict__ xw = x + (size_t)b0 * HW;

#pragma unroll
    for (int t = 0; t < 8; t++) {
        float4 xv = make_float4(0.f, 0.f, 0.f, 0.f);
        if (ok) xv = *reinterpret_cast<const float4*>(xw + (size_t)t * HW + off);

#pragma unroll
        for (int q = 0; q < 4; q++) {
            float s;
            s = fmaf(xv.x, wq[q].x, 0.f);
            s = fmaf(xv.y, wq[q].y, s);
            s = fmaf(xv.z, wq[q].z, s);
            s = fmaf(xv.w, wq[q].w, s);
            sred[warp][t][q][lane] = s;    // conflict-free STS.32
        }
    }

    __syncthreads();

    // Phase 2: thread -> (batch b = tid>>2, quadrant q = tid&3)
    {
        const int b = tid >> 2;            // 0..63
        const int q = tid & 3;
        const float4* row =
            reinterpret_cast<const float4*>(&sred[b >> 3][b & 7][q][0]);
        float4 s4 = make_float4(0.f, 0.f, 0.f, 0.f);
#pragma unroll
        for (int i = 0; i < 8; i++) {
            const float4 v = row[i];
            s4.x += v.x; s4.y += v.y; s4.z += v.z; s4.w += v.w;
        }
        const float s = (s4.x + s4.y) + (s4.z + s4.w);

        const int r = Ri - (q >> 1), c = Ci - (q & 1);
        if (r >= 0 && r < NKH && c >= 0 && c < NKW)
            atomicAdd(out + (size_t)b * NK + r * NKW + c, s);
    }
}

extern "C" void kernel_launch(void* const* d_in, const int* in_sizes, int n_in,
                              void* d_out, int out_size)
{
    const float* x      = (const float*)d_in[0];   // (64,1,512,512) fp32
    const float* weight = (const float*)d_in[1];   // (1024,1024)    fp32
    const float* bias   = (const float*)d_in[2];   // (1024,)        fp32
    float*       out    = (float*)d_out;           // (64,32,32)     fp32

    bslc_init<<<(BATCH * NK) / 256, 256>>>(bias, out);

    dim3 grid(NC * NC, 2);                         // 1089 x 2 half-cells
    bslc_main<<<grid, 256>>>(x, weight, out);
}